// round 1
// baseline (speedup 1.0000x reference)
#include <cuda_runtime.h>

#define Nn 1000
#define Bb 8

// Scratch (static __device__ — no allocation)
__device__ float4 g_EA[Nn];
__device__ float4 g_EB[Nn];
__device__ float4 g_xt[2 * Nn];   // xt[i] = x[0..7][i] transposed, 2 float4 per i
__device__ float  g_cc[32];       // c0/c1/c2 [k][m] (18) + Wf2v (3) + bf2v (1)

// ---------------------------------------------------------------------------
// Kernel 1: single block. Computes sx[i], X, all scalar coefficients, EA/EB,
// transposed x, and the message-combine constants.
// ---------------------------------------------------------------------------
__global__ void __launch_bounds__(256) k_pre(
    const float* __restrict__ x,
    const float* __restrict__ W1,   const float* __restrict__ b1,
    const float* __restrict__ W2,   const float* __restrict__ b2,
    const float* __restrict__ Wf1e, const float* __restrict__ bf1e,
    const float* __restrict__ Wf2e, const float* __restrict__ bf2e,
    const float* __restrict__ Wfk,  const float* __restrict__ bfk,
    const float* __restrict__ Wf1v, const float* __restrict__ bf1v,
    const float* __restrict__ Wf2v, const float* __restrict__ bf2v)
{
    __shared__ float s_sx[Nn];
    __shared__ float s_red[256];
    const int tid = threadIdx.x;

    float px = 0.f;
    for (int i = tid; i < Nn; i += 256) {
        float v[8]; float s = 0.f;
        #pragma unroll
        for (int b = 0; b < 8; b++) { v[b] = x[b * Nn + i]; s += v[b]; }
        g_xt[2 * i]     = make_float4(v[0], v[1], v[2], v[3]);
        g_xt[2 * i + 1] = make_float4(v[4], v[5], v[6], v[7]);
        s_sx[i] = s;
        px += s;
    }
    s_red[tid] = px;
    __syncthreads();
    for (int off = 128; off > 0; off >>= 1) {
        if (tid < off) s_red[tid] += s_red[tid + off];
        __syncthreads();
    }
    const float X = s_red[0];

    // --- scalar coefficients (computed redundantly per thread; ~200 flops) ---
    // h[b,i,f] = alpha_f * x[b,i] + beta_f * xs[b] + gamma_f
    float alpha[2], beta[2], gamma[2];
    #pragma unroll
    for (int f = 0; f < 2; f++) {
        float sa = 0.f, sb = 0.f, sg = 0.f;
        #pragma unroll
        for (int e = 0; e < 4; e++) {
            float we = Wf1e[(2 * e) * 2 + f];
            float wo = Wf1e[(2 * e + 1) * 2 + f];
            sa += W1[e] * we;
            sb += W1[e] * wo;
            sg += b1[e] * (we + wo);
        }
        alpha[f] = (float)Nn * sa;
        beta[f]  = sb;
        gamma[f] = (float)Nn * (sg + bf1e[f]);
    }
    // h2[b,i,v] = ap_v * x + bp_v * xs[b] + gp_v ; g[i,v] = ap_v*sx[i] + cv_v
    float ap[3], cv[3];
    #pragma unroll
    for (int vv = 0; vv < 3; vv++) {
        float a = 0.f, bq = 0.f, g = 0.f;
        #pragma unroll
        for (int f = 0; f < 2; f++) {
            float w = Wf1v[f * 3 + vv];
            a  += alpha[f] * w;
            bq += beta[f]  * w;
            g  += gamma[f] * w;
        }
        g += bf1v[vv];
        ap[vv] = a;
        cv[vv] = bq * X + (float)Bb * g;
    }
    // edge_logits[i,j,k] = aA_k*sx[i] + cA_k + aB_k*sx[j] + cB_k
    float aA[3], cA[3], aB[3], cB[3];
    #pragma unroll
    for (int k = 0; k < 3; k++) {
        float s1 = 0.f, s2 = 0.f, s3 = 0.f, s4 = 0.f;
        #pragma unroll
        for (int vv = 0; vv < 3; vv++) {
            float we = Wf2e[(2 * vv) * 3 + k];
            float wo = Wf2e[(2 * vv + 1) * 3 + k];
            s1 += ap[vv] * we;  s2 += cv[vv] * we;
            s3 += ap[vv] * wo;  s4 += cv[vv] * wo;
        }
        aA[k] = s1; cA[k] = s2 + bf2e[k];
        aB[k] = s3; cB[k] = s4;
    }

    // EA/EB with per-side max subtraction (exact for factorized softmax)
    for (int i = tid; i < Nn; i += 256) {
        float sxi = s_sx[i];
        float A0 = fmaf(aA[0], sxi, cA[0]);
        float A1 = fmaf(aA[1], sxi, cA[1]);
        float A2 = fmaf(aA[2], sxi, cA[2]);
        float mA = fmaxf(A0, fmaxf(A1, A2));
        g_EA[i] = make_float4(__expf(A0 - mA), __expf(A1 - mA), __expf(A2 - mA), 0.f);
        float B0 = fmaf(aB[0], sxi, cB[0]);
        float B1 = fmaf(aB[1], sxi, cB[1]);
        float B2 = fmaf(aB[2], sxi, cB[2]);
        float mB = fmaxf(B0, fmaxf(B1, B2));
        g_EB[i] = make_float4(__expf(B0 - mB), __expf(B1 - mB), __expf(B2 - mB), 0.f);
    }

    // Message-combine constants:
    // v_e[b,i,m] = sum_k (x_bi*c1[k,m] + c0[k,m]) * T[i,k] + c2[k,m] * U[b,i,k]
    if (tid == 0) {
        #pragma unroll
        for (int k = 0; k < 3; k++)
            #pragma unroll
            for (int m = 0; m < 2; m++) {
                float u1 = 0.f, v1 = 0.f, u2 = 0.f, v2 = 0.f;
                #pragma unroll
                for (int e = 0; e < 4; e++) {
                    float we = Wfk[k * 16 + (2 * e) * 2 + m];
                    float wo = Wfk[k * 16 + (2 * e + 1) * 2 + m];
                    u1 += W2[e] * we;  v1 += b2[e] * we;
                    u2 += W2[e] * wo;  v2 += b2[e] * wo;
                }
                int km = k * 2 + m;
                g_cc[km * 3 + 0] = v1 + v2 + bfk[km];  // c0
                g_cc[km * 3 + 1] = u1;                 // c1
                g_cc[km * 3 + 2] = u2;                 // c2
            }
        g_cc[18] = Wf2v[0]; g_cc[19] = Wf2v[1];
        g_cc[20] = Wf2v[2]; g_cc[21] = bf2v[0];
    }
}

// ---------------------------------------------------------------------------
// Kernel 2: one block per row i. Accumulates T[i,k] = sum_j p[i,j,k] and
// U[b,i,k] = sum_j p[i,j,k]*x[b,j] (the only true O(N^2) work), then threads
// 0..7 compute the 8 batch outputs for row i. Deterministic reduction.
// ---------------------------------------------------------------------------
__global__ void __launch_bounds__(128) k_main(float* __restrict__ out)
{
    const int i   = blockIdx.x;
    const int tid = threadIdx.x;
    const float4 ea = g_EA[i];

    float acc[27];
    #pragma unroll
    for (int v = 0; v < 27; v++) acc[v] = 0.f;

    for (int j = tid; j < Nn; j += 128) {
        float4 eb = g_EB[j];
        float4 xa = g_xt[2 * j];
        float4 xb = g_xt[2 * j + 1];
        float d = fmaf(ea.x, eb.x, fmaf(ea.y, eb.y, ea.z * eb.z));
        float r = __fdividef(1.f, d);
        float w0 = eb.x * r, w1 = eb.y * r, w2 = eb.z * r;
        acc[0] += w0; acc[1] += w1; acc[2] += w2;
        float xv[8] = {xa.x, xa.y, xa.z, xa.w, xb.x, xb.y, xb.z, xb.w};
        float w[3]  = {w0, w1, w2};
        #pragma unroll
        for (int b = 0; b < 8; b++)
            #pragma unroll
            for (int k = 0; k < 3; k++)
                acc[3 + b * 3 + k] = fmaf(w[k], xv[b], acc[3 + b * 3 + k]);
    }

    // warp-level butterfly reduce (deterministic)
    #pragma unroll
    for (int v = 0; v < 27; v++) {
        #pragma unroll
        for (int off = 16; off > 0; off >>= 1)
            acc[v] += __shfl_xor_sync(0xffffffffu, acc[v], off);
    }

    __shared__ float sred[4][28];
    const int warp = tid >> 5, lane = tid & 31;
    if (lane == 0) {
        #pragma unroll
        for (int v = 0; v < 27; v++) sred[warp][v] = acc[v];
    }
    __syncthreads();

    if (tid < 8) {
        const int b = tid;
        float T[3], U[3];
        #pragma unroll
        for (int k = 0; k < 3; k++) {
            T[k] = ((sred[0][k] + sred[1][k]) + (sred[2][k] + sred[3][k]));
            int v = 3 + b * 3 + k;
            U[k] = ((sred[0][v] + sred[1][v]) + (sred[2][v] + sred[3][v]));
        }
        float eav[3] = {ea.x, ea.y, ea.z};
        float xbi = ((const float*)&g_xt[2 * i])[b];
        float ve0 = 0.f, ve1 = 0.f;
        #pragma unroll
        for (int k = 0; k < 3; k++) {
            float Tk = eav[k] * T[k];
            float Uk = eav[k] * U[k];
            ve0 += fmaf(xbi, g_cc[(k * 2 + 0) * 3 + 1], g_cc[(k * 2 + 0) * 3 + 0]) * Tk
                 + g_cc[(k * 2 + 0) * 3 + 2] * Uk;
            ve1 += fmaf(xbi, g_cc[(k * 2 + 1) * 3 + 1], g_cc[(k * 2 + 1) * 3 + 0]) * Tk
                 + g_cc[(k * 2 + 1) * 3 + 2] * Uk;
        }
        out[b * Nn + i] = xbi * (1.f + g_cc[20]) + g_cc[21]
                        + ve0 * g_cc[18] + ve1 * g_cc[19];
    }
}

extern "C" void kernel_launch(void* const* d_in, const int* in_sizes, int n_in,
                              void* d_out, int out_size)
{
    (void)in_sizes; (void)n_in; (void)out_size;
    k_pre<<<1, 256>>>(
        (const float*)d_in[0],
        (const float*)d_in[1],  (const float*)d_in[2],
        (const float*)d_in[3],  (const float*)d_in[4],
        (const float*)d_in[5],  (const float*)d_in[6],
        (const float*)d_in[7],  (const float*)d_in[8],
        (const float*)d_in[9],  (const float*)d_in[10],
        (const float*)d_in[11], (const float*)d_in[12],
        (const float*)d_in[13], (const float*)d_in[14]);
    k_main<<<Nn, 128>>>((float*)d_out);
}

// round 2
// speedup vs baseline: 1.0019x; 1.0019x over previous
#include <cuda_runtime.h>

#define Nn   1000
#define NP   1024      // padded
#define Bb   8

// Scratch (static __device__ — no allocation). Padded to NP.
__device__ float4 g_EA[NP];
__device__ float4 g_EB[NP];       // pad rows = (0,0,0,1) -> d contribution 1, w = 0
__device__ float4 g_xt[2 * NP];   // xt[i] = x[0..7][i] transposed; pad rows = 0
__device__ float  g_cc[32];       // c0/c1/c2 [k][m] (18) + Wf2v (3) + bf2v (1)

// ---------------------------------------------------------------------------
// Kernel 1: single block, 1024 threads, single pass. Thread t owns row i=t.
// ---------------------------------------------------------------------------
__global__ void __launch_bounds__(1024) k_pre(
    const float* __restrict__ x,
    const float* __restrict__ W1,   const float* __restrict__ b1,
    const float* __restrict__ W2,   const float* __restrict__ b2,
    const float* __restrict__ Wf1e, const float* __restrict__ bf1e,
    const float* __restrict__ Wf2e, const float* __restrict__ bf2e,
    const float* __restrict__ Wfk,  const float* __restrict__ bfk,
    const float* __restrict__ Wf1v, const float* __restrict__ bf1v,
    const float* __restrict__ Wf2v, const float* __restrict__ bf2v)
{
    __shared__ float s_red[32];
    const int tid = threadIdx.x;
    const bool live = (tid < Nn);

    // --- load & transpose my row; sx in register ---
    float v[8];
    float sxi = 0.f;
    #pragma unroll
    for (int b = 0; b < 8; b++) {
        v[b] = live ? x[b * Nn + tid] : 0.f;
        sxi += v[b];
    }
    g_xt[2 * tid]     = make_float4(v[0], v[1], v[2], v[3]);
    g_xt[2 * tid + 1] = make_float4(v[4], v[5], v[6], v[7]);

    // --- global sum X: warp shfl + smem over 32 warps ---
    float px = sxi;
    #pragma unroll
    for (int off = 16; off > 0; off >>= 1)
        px += __shfl_xor_sync(0xffffffffu, px, off);
    if ((tid & 31) == 0) s_red[tid >> 5] = px;
    __syncthreads();
    if (tid < 32) {
        float t = s_red[tid];
        #pragma unroll
        for (int off = 16; off > 0; off >>= 1)
            t += __shfl_xor_sync(0xffffffffu, t, off);
        if (tid == 0) s_red[0] = t;
    }
    __syncthreads();
    const float X = s_red[0];

    // --- scalar coefficients (redundant per thread, ~300 flops) ---
    float alpha[2], beta[2], gamma[2];
    #pragma unroll
    for (int f = 0; f < 2; f++) {
        float sa = 0.f, sb = 0.f, sg = 0.f;
        #pragma unroll
        for (int e = 0; e < 4; e++) {
            float we = Wf1e[(2 * e) * 2 + f];
            float wo = Wf1e[(2 * e + 1) * 2 + f];
            sa += W1[e] * we;
            sb += W1[e] * wo;
            sg += b1[e] * (we + wo);
        }
        alpha[f] = (float)Nn * sa;
        beta[f]  = sb;
        gamma[f] = (float)Nn * (sg + bf1e[f]);
    }
    float ap[3], cv[3];
    #pragma unroll
    for (int vv = 0; vv < 3; vv++) {
        float a = 0.f, bq = 0.f, g = 0.f;
        #pragma unroll
        for (int f = 0; f < 2; f++) {
            float w = Wf1v[f * 3 + vv];
            a  += alpha[f] * w;
            bq += beta[f]  * w;
            g  += gamma[f] * w;
        }
        g += bf1v[vv];
        ap[vv] = a;
        cv[vv] = bq * X + (float)Bb * g;
    }
    float aA[3], cA[3], aB[3], cB[3];
    #pragma unroll
    for (int k = 0; k < 3; k++) {
        float s1 = 0.f, s2 = 0.f, s3 = 0.f, s4 = 0.f;
        #pragma unroll
        for (int vv = 0; vv < 3; vv++) {
            float we = Wf2e[(2 * vv) * 3 + k];
            float wo = Wf2e[(2 * vv + 1) * 3 + k];
            s1 += ap[vv] * we;  s2 += cv[vv] * we;
            s3 += ap[vv] * wo;  s4 += cv[vv] * wo;
        }
        aA[k] = s1; cA[k] = s2 + bf2e[k];
        aB[k] = s3; cB[k] = s4;
    }

    // --- EA/EB (per-side max-subtracted; exact for factorized softmax) ---
    if (live) {
        float A0 = fmaf(aA[0], sxi, cA[0]);
        float A1 = fmaf(aA[1], sxi, cA[1]);
        float A2 = fmaf(aA[2], sxi, cA[2]);
        float mA = fmaxf(A0, fmaxf(A1, A2));
        g_EA[tid] = make_float4(__expf(A0 - mA), __expf(A1 - mA), __expf(A2 - mA), 0.f);
        float B0 = fmaf(aB[0], sxi, cB[0]);
        float B1 = fmaf(aB[1], sxi, cB[1]);
        float B2 = fmaf(aB[2], sxi, cB[2]);
        float mB = fmaxf(B0, fmaxf(B1, B2));
        g_EB[tid] = make_float4(__expf(B0 - mB), __expf(B1 - mB), __expf(B2 - mB), 0.f);
    } else {
        g_EA[tid] = make_float4(0.f, 0.f, 0.f, 0.f);
        g_EB[tid] = make_float4(0.f, 0.f, 0.f, 1.f);  // pad: d += 1, w = 0
    }

    // --- message-combine constants ---
    if (tid == 0) {
        #pragma unroll
        for (int k = 0; k < 3; k++)
            #pragma unroll
            for (int m = 0; m < 2; m++) {
                float u1 = 0.f, v1 = 0.f, u2 = 0.f, v2 = 0.f;
                #pragma unroll
                for (int e = 0; e < 4; e++) {
                    float we = Wfk[k * 16 + (2 * e) * 2 + m];
                    float wo = Wfk[k * 16 + (2 * e + 1) * 2 + m];
                    u1 += W2[e] * we;  v1 += b2[e] * we;
                    u2 += W2[e] * wo;  v2 += b2[e] * wo;
                }
                int km = k * 2 + m;
                g_cc[km * 3 + 0] = v1 + v2 + bfk[km];  // c0
                g_cc[km * 3 + 1] = u1;                 // c1
                g_cc[km * 3 + 2] = u2;                 // c2
            }
        g_cc[18] = Wf2v[0]; g_cc[19] = Wf2v[1];
        g_cc[20] = Wf2v[2]; g_cc[21] = bf2v[0];
    }
}

// ---------------------------------------------------------------------------
// Kernel 2: one block (256 threads) per row i. Fully unrolled: each thread
// owns exactly 4 j's (NP = 4*256), all loads issued up front (MLP=12).
// ---------------------------------------------------------------------------
__global__ void __launch_bounds__(256) k_main(float* __restrict__ out)
{
    const int i   = blockIdx.x;
    const int tid = threadIdx.x;
    const float4 ea = g_EA[i];

    // Issue all 12 wide loads up front.
    float4 eb[4], xa[4], xb[4];
    #pragma unroll
    for (int m = 0; m < 4; m++) {
        int j = tid + 256 * m;
        eb[m] = g_EB[j];
        xa[m] = g_xt[2 * j];
        xb[m] = g_xt[2 * j + 1];
    }

    float acc[27];
    #pragma unroll
    for (int v = 0; v < 27; v++) acc[v] = 0.f;

    #pragma unroll
    for (int m = 0; m < 4; m++) {
        // pad rows have eb = (0,0,0,1): d = 1, w = 0, x = 0 -> no contribution
        float d = fmaf(ea.x, eb[m].x, fmaf(ea.y, eb[m].y, fmaf(ea.z, eb[m].z, eb[m].w)));
        float r = __fdividef(1.f, d);
        float w0 = eb[m].x * r, w1 = eb[m].y * r, w2 = eb[m].z * r;
        acc[0] += w0; acc[1] += w1; acc[2] += w2;
        float xv[8] = {xa[m].x, xa[m].y, xa[m].z, xa[m].w,
                       xb[m].x, xb[m].y, xb[m].z, xb[m].w};
        float w[3] = {w0, w1, w2};
        #pragma unroll
        for (int b = 0; b < 8; b++)
            #pragma unroll
            for (int k = 0; k < 3; k++)
                acc[3 + b * 3 + k] = fmaf(w[k], xv[b], acc[3 + b * 3 + k]);
    }

    // warp butterfly reduce (deterministic)
    #pragma unroll
    for (int v = 0; v < 27; v++) {
        #pragma unroll
        for (int off = 16; off > 0; off >>= 1)
            acc[v] += __shfl_xor_sync(0xffffffffu, acc[v], off);
    }

    __shared__ float sred[8][28];
    const int warp = tid >> 5, lane = tid & 31;
    if (lane == 0) {
        #pragma unroll
        for (int v = 0; v < 27; v++) sred[warp][v] = acc[v];
    }
    __syncthreads();

    if (tid < 8) {
        const int b = tid;
        float T[3], U[3];
        #pragma unroll
        for (int k = 0; k < 3; k++) {
            float t = 0.f, u = 0.f;
            #pragma unroll
            for (int w8 = 0; w8 < 8; w8++) {
                t += sred[w8][k];
                u += sred[w8][3 + b * 3 + k];
            }
            T[k] = t; U[k] = u;
        }
        float eav[3] = {ea.x, ea.y, ea.z};
        float xbi = ((const float*)&g_xt[2 * i])[b];
        float ve0 = 0.f, ve1 = 0.f;
        #pragma unroll
        for (int k = 0; k < 3; k++) {
            float Tk = eav[k] * T[k];
            float Uk = eav[k] * U[k];
            ve0 += fmaf(xbi, g_cc[(k * 2 + 0) * 3 + 1], g_cc[(k * 2 + 0) * 3 + 0]) * Tk
                 + g_cc[(k * 2 + 0) * 3 + 2] * Uk;
            ve1 += fmaf(xbi, g_cc[(k * 2 + 1) * 3 + 1], g_cc[(k * 2 + 1) * 3 + 0]) * Tk
                 + g_cc[(k * 2 + 1) * 3 + 2] * Uk;
        }
        out[b * Nn + i] = xbi * (1.f + g_cc[20]) + g_cc[21]
                        + ve0 * g_cc[18] + ve1 * g_cc[19];
    }
}

extern "C" void kernel_launch(void* const* d_in, const int* in_sizes, int n_in,
                              void* d_out, int out_size)
{
    (void)in_sizes; (void)n_in; (void)out_size;
    k_pre<<<1, 1024>>>(
        (const float*)d_in[0],
        (const float*)d_in[1],  (const float*)d_in[2],
        (const float*)d_in[3],  (const float*)d_in[4],
        (const float*)d_in[5],  (const float*)d_in[6],
        (const float*)d_in[7],  (const float*)d_in[8],
        (const float*)d_in[9],  (const float*)d_in[10],
        (const float*)d_in[11], (const float*)d_in[12],
        (const float*)d_in[13], (const float*)d_in[14]);
    k_main<<<Nn, 256>>>((float*)d_out);
}